// round 1
// baseline (speedup 1.0000x reference)
#include <cuda_runtime.h>
#include <math.h>

// ---------------- problem constants ----------------
#define Bsz   4
#define Ssz   2048
#define Esz   1024
#define Hsz   8
#define HDsz  128
#define ADsz  128
#define Mrows (Bsz * Ssz)          // 8192
#define N_UVQK 4096                // (2*HD + 2*AD) * H
#define N_PROJ 3072                // 3 * H * HD
#define ALPHA_SC 0.08838834764831845f   // 1/sqrt(128)
#define INV_S    (1.0f / 2048.0f)
#define LN_EPS   1e-6f

// ---------------- scratch (device globals; no allocation allowed) ----------------
__device__ float g_normx[(size_t)Mrows * Esz];    // 32 MB
__device__ float g_uvqk [(size_t)Mrows * N_UVQK]; // 128 MB
__device__ float g_attn [(size_t)Mrows * Esz];    // 32 MB
__device__ float g_proj [(size_t)Mrows * N_PROJ]; // 96 MB

// ---------------- helpers ----------------
__device__ __forceinline__ void blockReduce2(float& a, float& b) {
    // blockDim.x == 256 assumed
    #pragma unroll
    for (int off = 16; off > 0; off >>= 1) {
        a += __shfl_down_sync(0xffffffffu, a, off);
        b += __shfl_down_sync(0xffffffffu, b, off);
    }
    __shared__ float sa[8], sb[8];
    __shared__ float ra, rb;
    int w = threadIdx.x >> 5, l = threadIdx.x & 31;
    if (l == 0) { sa[w] = a; sb[w] = b; }
    __syncthreads();
    if (threadIdx.x == 0) {
        float ta = 0.f, tb = 0.f;
        #pragma unroll
        for (int i = 0; i < 8; i++) { ta += sa[i]; tb += sb[i]; }
        ra = ta; rb = tb;
    }
    __syncthreads();
    a = ra; b = rb;
}

__device__ __forceinline__ float silu_f(float x) {
    return x / (1.0f + expf(-x));
}

// ---------------- LayerNorm on input x -> g_normx ----------------
__global__ __launch_bounds__(256) void ln_in_kernel(
    const float* __restrict__ x, const float* __restrict__ sc,
    const float* __restrict__ bi, float* __restrict__ out)
{
    int row = blockIdx.x;
    int c = threadIdx.x * 4;
    const float* xr = x + (size_t)row * Esz;
    float4 v = *(const float4*)&xr[c];
    float s  = v.x + v.y + v.z + v.w;
    float ss = v.x*v.x + v.y*v.y + v.z*v.z + v.w*v.w;
    blockReduce2(s, ss);
    float mu = s * (1.0f / Esz);
    float rs = rsqrtf(ss * (1.0f / Esz) - mu * mu + LN_EPS);
    float4 s4 = *(const float4*)&sc[c];
    float4 b4 = *(const float4*)&bi[c];
    float4 o;
    o.x = (v.x - mu) * rs * s4.x + b4.x;
    o.y = (v.y - mu) * rs * s4.y + b4.y;
    o.z = (v.z - mu) * rs * s4.z + b4.z;
    o.w = (v.w - mu) * rs * s4.w + b4.w;
    *(float4*)&out[(size_t)row * Esz + c] = o;
}

// ---------------- generic 128x128x8 SGEMM: C = A@B (+bias per col)(+resid) ----------------
// A: M x K row-major, B: K x N row-major. M%128==0, N%128==0, K%8==0.
__global__ __launch_bounds__(256) void sgemm_kernel(
    const float* __restrict__ A, const float* __restrict__ Bm,
    float* __restrict__ C, int M, int N, int K,
    const float* __restrict__ bias, const float* __restrict__ resid)
{
    __shared__ float As[8][128];
    __shared__ float Bs[8][128];
    int tid = threadIdx.x;
    int bx = blockIdx.x, by = blockIdx.y;
    int aRow = tid >> 1, aCol = (tid & 1) * 4;
    int bRow = tid >> 5, bCol = (tid & 31) * 4;
    const float* Ap = A + (size_t)(by * 128 + aRow) * K + aCol;
    const float* Bp = Bm + (size_t)bRow * N + bx * 128 + bCol;
    int tx = tid & 15, ty = tid >> 4;

    float acc[8][8];
    #pragma unroll
    for (int i = 0; i < 8; i++)
        #pragma unroll
        for (int j = 0; j < 8; j++) acc[i][j] = 0.f;

    for (int k0 = 0; k0 < K; k0 += 8) {
        float4 av = *(const float4*)Ap;
        float4 bv = *(const float4*)Bp;
        As[aCol + 0][aRow] = av.x;
        As[aCol + 1][aRow] = av.y;
        As[aCol + 2][aRow] = av.z;
        As[aCol + 3][aRow] = av.w;
        *(float4*)&Bs[bRow][bCol] = bv;
        __syncthreads();
        #pragma unroll
        for (int kk = 0; kk < 8; kk++) {
            float a[8], bb[8];
            *(float4*)&a[0]  = *(float4*)&As[kk][ty * 8];
            *(float4*)&a[4]  = *(float4*)&As[kk][ty * 8 + 4];
            *(float4*)&bb[0] = *(float4*)&Bs[kk][tx * 8];
            *(float4*)&bb[4] = *(float4*)&Bs[kk][tx * 8 + 4];
            #pragma unroll
            for (int i = 0; i < 8; i++)
                #pragma unroll
                for (int j = 0; j < 8; j++)
                    acc[i][j] += a[i] * bb[j];
        }
        __syncthreads();
        Ap += 8;
        Bp += (size_t)8 * N;
    }

    int rowBase = by * 128 + ty * 8;
    int colBase = bx * 128 + tx * 8;
    #pragma unroll
    for (int i = 0; i < 8; i++) {
        size_t off = (size_t)(rowBase + i) * N + colBase;
        #pragma unroll
        for (int j = 0; j < 8; j++) {
            float v = acc[i][j];
            if (bias)  v += bias[colBase + j];
            if (resid) v += resid[off + j];
            C[off + j] = v;
        }
    }
}

// ---------------- silu(u_proj) -> proj[:, 0:1024] ----------------
__global__ __launch_bounds__(256) void silu_kernel(
    const float* __restrict__ uvqk, float* __restrict__ proj)
{
    int idx = blockIdx.x * 256 + threadIdx.x;   // 8192 * 256 threads
    int row = idx >> 8;
    int c = (idx & 255) * 4;
    float4 v = *(const float4*)&uvqk[(size_t)row * N_UVQK + c];
    v.x = silu_f(v.x); v.y = silu_f(v.y); v.z = silu_f(v.z); v.w = silu_f(v.w);
    *(float4*)&proj[(size_t)row * N_PROJ + c] = v;
}

// ---------------- fused attention ----------------
// per block: (b, h, 32 query rows). Loop over K tiles of 32.
// attn_w = silu(q.k * alpha)/S * mask ; O += attn_w @ V
__global__ __launch_bounds__(256) void attn_kernel(
    const float* __restrict__ uvqk, const int* __restrict__ num_targets,
    float* __restrict__ attn_out)
{
    __shared__ float Qs[32][132];
    __shared__ float KVs[32][132];
    __shared__ float Ws[32][32];

    int tid = threadIdx.x;
    int b = blockIdx.z, h = blockIdx.y;
    int q0 = blockIdx.x * 32;
    int maxid = Ssz - num_targets[b];

    const size_t rstride = N_UVQK;
    const float* qbase = uvqk + (size_t)(b * Ssz) * rstride + 2048 + h * 128;
    const float* kbase = uvqk + (size_t)(b * Ssz) * rstride + 3072 + h * 128;
    const float* vbase = uvqk + (size_t)(b * Ssz) * rstride + 1024 + h * 128;

    #pragma unroll
    for (int ii = 0; ii < 4; ii++) {
        int lin = tid + ii * 256;
        int r = lin >> 5, c4 = (lin & 31) << 2;
        *(float4*)&Qs[r][c4] = *(const float4*)&qbase[(size_t)(q0 + r) * rstride + c4];
    }

    float o[4][4] = {};
    int sy = tid >> 4, sx = tid & 15;
    int r0 = sy * 2, c0 = sx * 2;
    int org = (tid >> 5) << 2;
    int oc  = (tid & 31) << 2;

    for (int k0 = 0; k0 < Ssz; k0 += 32) {
        __syncthreads();   // protect KVs/Ws reuse from previous iteration
        #pragma unroll
        for (int ii = 0; ii < 4; ii++) {
            int lin = tid + ii * 256;
            int r = lin >> 5, c4 = (lin & 31) << 2;
            *(float4*)&KVs[r][c4] = *(const float4*)&kbase[(size_t)(k0 + r) * rstride + c4];
        }
        __syncthreads();

        float s00 = 0.f, s01 = 0.f, s10 = 0.f, s11 = 0.f;
        #pragma unroll
        for (int d = 0; d < 128; d += 4) {
            float4 qa = *(float4*)&Qs[r0][d];
            float4 qb = *(float4*)&Qs[r0 + 1][d];
            float4 ka = *(float4*)&KVs[c0][d];
            float4 kb = *(float4*)&KVs[c0 + 1][d];
            s00 += qa.x*ka.x + qa.y*ka.y + qa.z*ka.z + qa.w*ka.w;
            s01 += qa.x*kb.x + qa.y*kb.y + qa.z*kb.z + qa.w*kb.w;
            s10 += qb.x*ka.x + qb.y*ka.y + qb.z*ka.z + qb.w*ka.w;
            s11 += qb.x*kb.x + qb.y*kb.y + qb.z*kb.z + qb.w*kb.w;
        }
        {
            float sv[2][2] = {{s00, s01}, {s10, s11}};
            #pragma unroll
            for (int i = 0; i < 2; i++) {
                int qg = q0 + r0 + i;
                int idq = min(qg, maxid);
                #pragma unroll
                for (int j = 0; j < 2; j++) {
                    int kg = k0 + c0 + j;
                    int idk = min(kg, maxid);
                    bool valid = (qg == kg) || (idq > idk);
                    float scv = sv[i][j] * ALPHA_SC;
                    float w = valid ? silu_f(scv) * INV_S : 0.f;
                    Ws[r0 + i][c0 + j] = w;
                }
            }
        }
        __syncthreads();   // Ws written; KVs reads done -> safe to overwrite with V
        #pragma unroll
        for (int ii = 0; ii < 4; ii++) {
            int lin = tid + ii * 256;
            int r = lin >> 5, c4 = (lin & 31) << 2;
            *(float4*)&KVs[r][c4] = *(const float4*)&vbase[(size_t)(k0 + r) * rstride + c4];
        }
        __syncthreads();
        #pragma unroll
        for (int kk = 0; kk < 32; kk++) {
            float4 v = *(float4*)&KVs[kk][oc];
            float w0 = Ws[org + 0][kk];
            float w1 = Ws[org + 1][kk];
            float w2 = Ws[org + 2][kk];
            float w3 = Ws[org + 3][kk];
            o[0][0] += w0*v.x; o[0][1] += w0*v.y; o[0][2] += w0*v.z; o[0][3] += w0*v.w;
            o[1][0] += w1*v.x; o[1][1] += w1*v.y; o[1][2] += w1*v.z; o[1][3] += w1*v.w;
            o[2][0] += w2*v.x; o[2][1] += w2*v.y; o[2][2] += w2*v.z; o[2][3] += w2*v.w;
            o[3][0] += w3*v.x; o[3][1] += w3*v.y; o[3][2] += w3*v.z; o[3][3] += w3*v.w;
        }
    }

    #pragma unroll
    for (int i = 0; i < 4; i++) {
        float4 v = make_float4(o[i][0], o[i][1], o[i][2], o[i][3]);
        *(float4*)&attn_out[(size_t)(b * Ssz + q0 + org + i) * Esz + h * 128 + oc] = v;
    }
}

// ---------------- post-attention: LN(attn), gate, fill proj[:,1024:3072] ----------------
__global__ __launch_bounds__(256) void postattn_kernel(
    const float* __restrict__ attn, const float* __restrict__ sc,
    const float* __restrict__ bi, float* __restrict__ proj)
{
    int row = blockIdx.x;
    int c = threadIdx.x * 4;
    const float* ar = attn + (size_t)row * Esz;
    float4 a = *(const float4*)&ar[c];
    float s  = a.x + a.y + a.z + a.w;
    float ss = a.x*a.x + a.y*a.y + a.z*a.z + a.w*a.w;
    blockReduce2(s, ss);
    float mu = s * (1.0f / Esz);
    float rs = rsqrtf(ss * (1.0f / Esz) - mu * mu + LN_EPS);
    float4 s4 = *(const float4*)&sc[c];
    float4 b4 = *(const float4*)&bi[c];
    float4 n;
    n.x = (a.x - mu) * rs * s4.x + b4.x;
    n.y = (a.y - mu) * rs * s4.y + b4.y;
    n.z = (a.z - mu) * rs * s4.z + b4.z;
    n.w = (a.w - mu) * rs * s4.w + b4.w;
    float* pr = proj + (size_t)row * N_PROJ;
    float4 u = *(const float4*)&pr[c];         // silu(u) already stored
    *(float4*)&pr[1024 + c] = a;               // attn
    float4 g;
    g.x = u.x * n.x; g.y = u.y * n.y; g.z = u.z * n.z; g.w = u.w * n.w;
    *(float4*)&pr[2048 + c] = g;               // gated
}

// ---------------- launch ----------------
extern "C" void kernel_launch(void* const* d_in, const int* in_sizes, int n_in,
                              void* d_out, int out_size)
{
    const float* x           = (const float*)d_in[0];
    const int*   num_targets = (const int*)  d_in[1];
    const float* uvqk_w      = (const float*)d_in[2];
    const float* uvqk_beta   = (const float*)d_in[3];
    const float* out_w       = (const float*)d_in[4];
    const float* in_scale    = (const float*)d_in[5];
    const float* in_bias     = (const float*)d_in[6];
    const float* out_scale   = (const float*)d_in[7];
    const float* out_bias    = (const float*)d_in[8];
    float* out = (float*)d_out;

    float *normx, *uvqk, *attn, *proj;
    cudaGetSymbolAddress((void**)&normx, g_normx);
    cudaGetSymbolAddress((void**)&uvqk,  g_uvqk);
    cudaGetSymbolAddress((void**)&attn,  g_attn);
    cudaGetSymbolAddress((void**)&proj,  g_proj);

    // 1) LayerNorm input
    ln_in_kernel<<<Mrows, 256>>>(x, in_scale, in_bias, normx);

    // 2) UVQK GEMM: (8192 x 1024) @ (1024 x 4096) + beta
    sgemm_kernel<<<dim3(N_UVQK / 128, Mrows / 128), 256>>>(
        normx, uvqk_w, uvqk, Mrows, N_UVQK, Esz, uvqk_beta, nullptr);

    // 3) silu(u_proj) -> proj[:, 0:1024]
    silu_kernel<<<Mrows, 256>>>(uvqk, proj);

    // 4) attention -> attn (B,S,H*HD)
    attn_kernel<<<dim3(Ssz / 32, Hsz, Bsz), 256>>>(uvqk, num_targets, attn);

    // 5) LN(attn) + gate -> proj[:, 1024:2048]=attn, proj[:, 2048:3072]=u*LN(attn)
    postattn_kernel<<<Mrows, 256>>>(attn, out_scale, out_bias, proj);

    // 6) output GEMM with fused residual: out = x + proj @ out_w
    sgemm_kernel<<<dim3(Esz / 128, Mrows / 128), 256>>>(
        proj, out_w, out, Mrows, Esz, N_PROJ, nullptr, x);
}

// round 4
// speedup vs baseline: 2.0942x; 2.0942x over previous
#include <cuda_runtime.h>
#include <math.h>
#include <stdint.h>

// ---------------- problem constants ----------------
#define Bsz   4
#define Ssz   2048
#define Esz   1024
#define Hsz   8
#define Mrows (Bsz * Ssz)          // 8192
#define N_UVQK 4096
#define N_PROJ 3072
#define ALPHA_SC 0.08838834764831845f   // 1/sqrt(128)
#define INV_S    (1.0f / 2048.0f)
#define LN_EPS   1e-6f

// ---------------- scratch (device globals; no allocation allowed) ----------------
__device__ float g_normx[(size_t)Mrows * Esz];    // 32 MB
__device__ float g_uvqk [(size_t)Mrows * N_UVQK]; // 128 MB
__device__ float g_attn [(size_t)Mrows * Esz];    // 32 MB
__device__ float g_proj [(size_t)Mrows * N_PROJ]; // 96 MB

// ---------------- helpers ----------------
__device__ __forceinline__ uint32_t f2tf32(float x) {
    uint32_t r;
    asm("cvt.rna.tf32.f32 %0, %1;" : "=r"(r) : "f"(x));
    return r;
}

__device__ __forceinline__ void mma_tf32(float* d,
    uint32_t a0, uint32_t a1, uint32_t a2, uint32_t a3,
    uint32_t b0, uint32_t b1)
{
    asm volatile(
        "mma.sync.aligned.m16n8k8.row.col.f32.tf32.tf32.f32 "
        "{%0,%1,%2,%3}, {%4,%5,%6,%7}, {%8,%9}, {%0,%1,%2,%3};\n"
        : "+f"(d[0]), "+f"(d[1]), "+f"(d[2]), "+f"(d[3])
        : "r"(a0), "r"(a1), "r"(a2), "r"(a3), "r"(b0), "r"(b1));
}

__device__ __forceinline__ float silu_f(float x) {
    return x / (1.0f + expf(-x));
}

__device__ __forceinline__ void blockReduce2(float& a, float& b) {
    #pragma unroll
    for (int off = 16; off > 0; off >>= 1) {
        a += __shfl_down_sync(0xffffffffu, a, off);
        b += __shfl_down_sync(0xffffffffu, b, off);
    }
    __shared__ float sa[8], sb[8];
    __shared__ float ra, rb;
    int w = threadIdx.x >> 5, l = threadIdx.x & 31;
    if (l == 0) { sa[w] = a; sb[w] = b; }
    __syncthreads();
    if (threadIdx.x == 0) {
        float ta = 0.f, tb = 0.f;
        #pragma unroll
        for (int i = 0; i < 8; i++) { ta += sa[i]; tb += sb[i]; }
        ra = ta; rb = tb;
    }
    __syncthreads();
    a = ra; b = rb;
}

// ---------------- LayerNorm on input x -> g_normx ----------------
__global__ __launch_bounds__(256) void ln_in_kernel(
    const float* __restrict__ x, const float* __restrict__ sc,
    const float* __restrict__ bi, float* __restrict__ out)
{
    int row = blockIdx.x;
    int c = threadIdx.x * 4;
    const float* xr = x + (size_t)row * Esz;
    float4 v = *(const float4*)&xr[c];
    float s  = v.x + v.y + v.z + v.w;
    float ss = v.x*v.x + v.y*v.y + v.z*v.z + v.w*v.w;
    blockReduce2(s, ss);
    float mu = s * (1.0f / Esz);
    float rs = rsqrtf(ss * (1.0f / Esz) - mu * mu + LN_EPS);
    float4 s4 = *(const float4*)&sc[c];
    float4 b4 = *(const float4*)&bi[c];
    float4 o;
    o.x = (v.x - mu) * rs * s4.x + b4.x;
    o.y = (v.y - mu) * rs * s4.y + b4.y;
    o.z = (v.z - mu) * rs * s4.z + b4.z;
    o.w = (v.w - mu) * rs * s4.w + b4.w;
    *(float4*)&out[(size_t)row * Esz + c] = o;
}

// ---------------- tf32 tensor-core GEMM: C = A@B (+bias)(+resid)(+silu tap) --
// A: MxK row-major fp32. B: KxN row-major fp32. Block tile 128x128, kTile 16.
// 8 warps in 2(M) x 4(N): warp tile 64x32 via m16n8k8.
// If silu_dst != null: for columns < 1024 also write silu(v) to
// silu_dst[row * N_PROJ + col]  (fuses the u -> silu(u) pass of GEMM1).
__global__ __launch_bounds__(256) void gemm_tf32_kernel(
    const float* __restrict__ A, const float* __restrict__ Bm,
    float* __restrict__ C, int M, int N, int K,
    const float* __restrict__ bias, const float* __restrict__ resid,
    float* __restrict__ silu_dst)
{
    __shared__ uint32_t As[16][132];   // [k][m] (transposed)
    __shared__ uint32_t Bs[16][132];   // [k][n]

    int tid = threadIdx.x;
    int wid = tid >> 5, lane = tid & 31;
    int gID = lane >> 2, tig = lane & 3;
    int warpM = wid & 1, warpN = wid >> 1;
    int bx = blockIdx.x, by = blockIdx.y;

    int arow = tid >> 1, acol = (tid & 1) * 8;
    int brow = tid >> 4, bcol = (tid & 15) * 8;
    const float* Aload = A + (size_t)(by * 128 + arow) * K + acol;
    const float* Bload = Bm + (size_t)brow * N + bx * 128 + bcol;

    float acc[4][4][4];
    #pragma unroll
    for (int i = 0; i < 4; i++)
        #pragma unroll
        for (int j = 0; j < 4; j++)
            #pragma unroll
            for (int q = 0; q < 4; q++) acc[i][j][q] = 0.f;

    float4 pa0, pa1, pb0, pb1;
    pa0 = *(const float4*)Aload;       pa1 = *(const float4*)(Aload + 4);
    pb0 = *(const float4*)Bload;       pb1 = *(const float4*)(Bload + 4);

    auto store_tiles = [&]() {
        As[acol + 0][arow] = f2tf32(pa0.x);
        As[acol + 1][arow] = f2tf32(pa0.y);
        As[acol + 2][arow] = f2tf32(pa0.z);
        As[acol + 3][arow] = f2tf32(pa0.w);
        As[acol + 4][arow] = f2tf32(pa1.x);
        As[acol + 5][arow] = f2tf32(pa1.y);
        As[acol + 6][arow] = f2tf32(pa1.z);
        As[acol + 7][arow] = f2tf32(pa1.w);
        Bs[brow][bcol + 0] = f2tf32(pb0.x);
        Bs[brow][bcol + 1] = f2tf32(pb0.y);
        Bs[brow][bcol + 2] = f2tf32(pb0.z);
        Bs[brow][bcol + 3] = f2tf32(pb0.w);
        Bs[brow][bcol + 4] = f2tf32(pb1.x);
        Bs[brow][bcol + 5] = f2tf32(pb1.y);
        Bs[brow][bcol + 6] = f2tf32(pb1.z);
        Bs[brow][bcol + 7] = f2tf32(pb1.w);
    };

    store_tiles();
    __syncthreads();

    for (int k0 = 0; k0 < K; k0 += 16) {
        bool more = (k0 + 16) < K;
        if (more) {
            Aload += 16;
            Bload += (size_t)16 * N;
            pa0 = *(const float4*)Aload;  pa1 = *(const float4*)(Aload + 4);
            pb0 = *(const float4*)Bload;  pb1 = *(const float4*)(Bload + 4);
        }
        #pragma unroll
        for (int ks = 0; ks < 2; ks++) {
            int kb = ks * 8;
            uint32_t af[4][4], bf[4][2];
            #pragma unroll
            for (int i = 0; i < 4; i++) {
                int m = warpM * 64 + i * 16 + gID;
                af[i][0] = As[kb + tig][m];
                af[i][1] = As[kb + tig][m + 8];
                af[i][2] = As[kb + tig + 4][m];
                af[i][3] = As[kb + tig + 4][m + 8];
            }
            #pragma unroll
            for (int j = 0; j < 4; j++) {
                int n = warpN * 32 + j * 8 + gID;
                bf[j][0] = Bs[kb + tig][n];
                bf[j][1] = Bs[kb + tig + 4][n];
            }
            #pragma unroll
            for (int i = 0; i < 4; i++)
                #pragma unroll
                for (int j = 0; j < 4; j++)
                    mma_tf32(acc[i][j], af[i][0], af[i][1], af[i][2], af[i][3],
                             bf[j][0], bf[j][1]);
        }
        __syncthreads();
        if (more) store_tiles();
        __syncthreads();
    }

    // epilogue
    bool siluTile = (silu_dst != nullptr) && (bx * 128 < 1024);
    #pragma unroll
    for (int i = 0; i < 4; i++) {
        int r0 = by * 128 + warpM * 64 + i * 16 + gID;
        #pragma unroll
        for (int j = 0; j < 4; j++) {
            int cg = bx * 128 + warpN * 32 + j * 8 + tig * 2;
            float v0 = acc[i][j][0], v1 = acc[i][j][1];
            float v2 = acc[i][j][2], v3 = acc[i][j][3];
            if (bias) {
                float b0 = bias[cg], b1 = bias[cg + 1];
                v0 += b0; v1 += b1; v2 += b0; v3 += b1;
            }
            size_t o0 = (size_t)r0 * N + cg;
            size_t o1 = (size_t)(r0 + 8) * N + cg;
            if (resid) {
                v0 += resid[o0]; v1 += resid[o0 + 1];
                v2 += resid[o1]; v3 += resid[o1 + 1];
            }
            *(float2*)&C[o0] = make_float2(v0, v1);
            *(float2*)&C[o1] = make_float2(v2, v3);
            if (siluTile) {
                size_t p0 = (size_t)r0 * N_PROJ + cg;
                size_t p1 = (size_t)(r0 + 8) * N_PROJ + cg;
                *(float2*)&silu_dst[p0] = make_float2(silu_f(v0), silu_f(v1));
                *(float2*)&silu_dst[p1] = make_float2(silu_f(v2), silu_f(v3));
            }
        }
    }
}

// ---------------- tensor-core fused attention ----------------
// block = (b, h, 64 q rows). 256 threads / 8 warps. Two tf32 GEMMs per K-tile(64):
//   S = Q @ K^T  (64x64x128), then mask/silu -> Ws, then O += Ws @ V (64x128x64)
// Dynamic smem layout (uint32 words):
//   Qs [64][132] @ 0      Ks [64][132] @ 8448
//   Vs [64][132] @ 16896  Ws [64][68]  @ 25344     total 29696 words = 118784 B
#define QS(r,c) sm[(r) * 132 + (c)]
#define KS(r,c) sm[8448 + (r) * 132 + (c)]
#define VS(r,c) sm[16896 + (r) * 132 + (c)]
#define WS(r,c) sm[25344 + (r) * 68 + (c)]
#define ATTN_SMEM_BYTES (29696 * 4)

__global__ __launch_bounds__(256) void attn_tc_kernel(
    const float* __restrict__ uvqk, const int* __restrict__ num_targets,
    float* __restrict__ attn_out)
{
    extern __shared__ uint32_t sm[];
    int tid = threadIdx.x;
    int wid = tid >> 5, lane = tid & 31;
    int gID = lane >> 2, tig = lane & 3;
    int b = blockIdx.z, h = blockIdx.y;
    int q0 = blockIdx.x * 64;
    int maxid = Ssz - num_targets[b];

    const size_t rstride = N_UVQK;
    const float* qbase = uvqk + (size_t)(b * Ssz) * rstride + 2048 + h * 128;
    const float* kbase = uvqk + (size_t)(b * Ssz) * rstride + 3072 + h * 128;
    const float* vbase = uvqk + (size_t)(b * Ssz) * rstride + 1024 + h * 128;

    // load Q tile (64 x 128)
    {
        int r = tid >> 2, cb = (tid & 3) * 32;
        const float* src = qbase + (size_t)(q0 + r) * rstride + cb;
        #pragma unroll
        for (int x = 0; x < 8; x++) {
            float4 v = *(const float4*)(src + x * 4);
            QS(r, cb + x * 4 + 0) = f2tf32(v.x);
            QS(r, cb + x * 4 + 1) = f2tf32(v.y);
            QS(r, cb + x * 4 + 2) = f2tf32(v.z);
            QS(r, cb + x * 4 + 3) = f2tf32(v.w);
        }
    }

    // score warps: 4(M) x 2(N); output warps: 2(M) x 4(N)
    int sWM = wid & 3, sWN = wid >> 2;
    int oWM = wid & 1, oWN = wid >> 1;

    float acc_o[2][4][4];
    #pragma unroll
    for (int i = 0; i < 2; i++)
        #pragma unroll
        for (int j = 0; j < 4; j++)
            #pragma unroll
            for (int q = 0; q < 4; q++) acc_o[i][j][q] = 0.f;

    int ldr = tid >> 2, ldc = (tid & 3) * 32;

    for (int k0 = 0; k0 < Ssz; k0 += 64) {
        __syncthreads();   // previous iteration's reads of Ks/Vs/Ws complete
        // load K and V tiles (64 x 128 each)
        {
            const float* ksrc = kbase + (size_t)(k0 + ldr) * rstride + ldc;
            const float* vsrc = vbase + (size_t)(k0 + ldr) * rstride + ldc;
            #pragma unroll
            for (int x = 0; x < 8; x++) {
                float4 kv = *(const float4*)(ksrc + x * 4);
                KS(ldr, ldc + x * 4 + 0) = f2tf32(kv.x);
                KS(ldr, ldc + x * 4 + 1) = f2tf32(kv.y);
                KS(ldr, ldc + x * 4 + 2) = f2tf32(kv.z);
                KS(ldr, ldc + x * 4 + 3) = f2tf32(kv.w);
            }
            #pragma unroll
            for (int x = 0; x < 8; x++) {
                float4 vv = *(const float4*)(vsrc + x * 4);
                VS(ldr, ldc + x * 4 + 0) = f2tf32(vv.x);
                VS(ldr, ldc + x * 4 + 1) = f2tf32(vv.y);
                VS(ldr, ldc + x * 4 + 2) = f2tf32(vv.z);
                VS(ldr, ldc + x * 4 + 3) = f2tf32(vv.w);
            }
        }
        __syncthreads();

        // scores: S(64x64) = Q(64x128) @ K^T
        float acc_s[4][4];
        #pragma unroll
        for (int j = 0; j < 4; j++)
            #pragma unroll
            for (int q = 0; q < 4; q++) acc_s[j][q] = 0.f;

        #pragma unroll
        for (int ks = 0; ks < 16; ks++) {
            int kb = ks * 8;
            int m = sWM * 16 + gID;
            uint32_t a0 = QS(m, kb + tig);
            uint32_t a1 = QS(m + 8, kb + tig);
            uint32_t a2 = QS(m, kb + tig + 4);
            uint32_t a3 = QS(m + 8, kb + tig + 4);
            #pragma unroll
            for (int j = 0; j < 4; j++) {
                int n = sWN * 32 + j * 8 + gID;
                uint32_t b0 = KS(n, kb + tig);
                uint32_t b1 = KS(n, kb + tig + 4);
                mma_tf32(acc_s[j], a0, a1, a2, a3, b0, b1);
            }
        }

        // mask + silu -> Ws
        {
            int rowL = sWM * 16 + gID;
            int qg0 = q0 + rowL;
            int qg1 = qg0 + 8;
            int idq0 = min(qg0, maxid);
            int idq1 = min(qg1, maxid);
            #pragma unroll
            for (int j = 0; j < 4; j++) {
                int colL = sWN * 32 + j * 8 + tig * 2;
                #pragma unroll
                for (int cc = 0; cc < 2; cc++) {
                    int kg = k0 + colL + cc;
                    int idk = min(kg, maxid);
                    float s0 = acc_s[j][cc] * ALPHA_SC;
                    float s1 = acc_s[j][cc + 2] * ALPHA_SC;
                    bool v0 = (qg0 == kg) || (idq0 > idk);
                    bool v1 = (qg1 == kg) || (idq1 > idk);
                    float w0 = v0 ? silu_f(s0) * INV_S : 0.f;
                    float w1 = v1 ? silu_f(s1) * INV_S : 0.f;
                    WS(rowL, colL + cc)     = f2tf32(w0);
                    WS(rowL + 8, colL + cc) = f2tf32(w1);
                }
            }
        }
        __syncthreads();

        // O += Ws(64x64) @ V(64x128)
        #pragma unroll
        for (int ks = 0; ks < 8; ks++) {
            int kb = ks * 8;
            uint32_t af[2][4];
            #pragma unroll
            for (int i = 0; i < 2; i++) {
                int m = oWM * 32 + i * 16 + gID;
                af[i][0] = WS(m, kb + tig);
                af[i][1] = WS(m + 8, kb + tig);
                af[i][2] = WS(m, kb + tig + 4);
                af[i][3] = WS(m + 8, kb + tig + 4);
            }
            #pragma unroll
            for (int j = 0; j < 4; j++) {
                int n = oWN * 32 + j * 8 + gID;
                uint32_t b0 = VS(kb + tig, n);
                uint32_t b1 = VS(kb + tig + 4, n);
                #pragma unroll
                for (int i = 0; i < 2; i++)
                    mma_tf32(acc_o[i][j], af[i][0], af[i][1], af[i][2], af[i][3],
                             b0, b1);
            }
        }
    }

    // epilogue
    #pragma unroll
    for (int i = 0; i < 2; i++) {
        int rowL = oWM * 32 + i * 16 + gID;
        size_t grow0 = (size_t)(b * Ssz + q0 + rowL) * Esz;
        size_t grow1 = (size_t)(b * Ssz + q0 + rowL + 8) * Esz;
        #pragma unroll
        for (int j = 0; j < 4; j++) {
            int col = h * 128 + oWN * 32 + j * 8 + tig * 2;
            *(float2*)&attn_out[grow0 + col] = make_float2(acc_o[i][j][0], acc_o[i][j][1]);
            *(float2*)&attn_out[grow1 + col] = make_float2(acc_o[i][j][2], acc_o[i][j][3]);
        }
    }
}

// ---------------- post-attention: LN(attn), gate, fill proj ----------------
__global__ __launch_bounds__(256) void postattn_kernel(
    const float* __restrict__ attn, const float* __restrict__ sc,
    const float* __restrict__ bi, float* __restrict__ proj)
{
    int row = blockIdx.x;
    int c = threadIdx.x * 4;
    const float* ar = attn + (size_t)row * Esz;
    float4 a = *(const float4*)&ar[c];
    float s  = a.x + a.y + a.z + a.w;
    float ss = a.x*a.x + a.y*a.y + a.z*a.z + a.w*a.w;
    blockReduce2(s, ss);
    float mu = s * (1.0f / Esz);
    float rs = rsqrtf(ss * (1.0f / Esz) - mu * mu + LN_EPS);
    float4 s4 = *(const float4*)&sc[c];
    float4 b4 = *(const float4*)&bi[c];
    float4 n;
    n.x = (a.x - mu) * rs * s4.x + b4.x;
    n.y = (a.y - mu) * rs * s4.y + b4.y;
    n.z = (a.z - mu) * rs * s4.z + b4.z;
    n.w = (a.w - mu) * rs * s4.w + b4.w;
    float* pr = proj + (size_t)row * N_PROJ;
    float4 u = *(const float4*)&pr[c];
    *(float4*)&pr[1024 + c] = a;
    float4 g;
    g.x = u.x * n.x; g.y = u.y * n.y; g.z = u.z * n.z; g.w = u.w * n.w;
    *(float4*)&pr[2048 + c] = g;
}

// ---------------- launch ----------------
extern "C" void kernel_launch(void* const* d_in, const int* in_sizes, int n_in,
                              void* d_out, int out_size)
{
    const float* x           = (const float*)d_in[0];
    const int*   num_targets = (const int*)  d_in[1];
    const float* uvqk_w      = (const float*)d_in[2];
    const float* uvqk_beta   = (const float*)d_in[3];
    const float* out_w       = (const float*)d_in[4];
    const float* in_scale    = (const float*)d_in[5];
    const float* in_bias     = (const float*)d_in[6];
    const float* out_scale   = (const float*)d_in[7];
    const float* out_bias    = (const float*)d_in[8];
    float* out = (float*)d_out;

    float *normx, *uvqk, *attn, *proj;
    cudaGetSymbolAddress((void**)&normx, g_normx);
    cudaGetSymbolAddress((void**)&uvqk,  g_uvqk);
    cudaGetSymbolAddress((void**)&attn,  g_attn);
    cudaGetSymbolAddress((void**)&proj,  g_proj);

    // idempotent, capture-safe (not a stream operation); no static state
    cudaFuncSetAttribute(attn_tc_kernel,
                         cudaFuncAttributeMaxDynamicSharedMemorySize,
                         ATTN_SMEM_BYTES);

    // 1) LayerNorm input
    ln_in_kernel<<<Mrows, 256>>>(x, in_scale, in_bias, normx);

    // 2) UVQK GEMM: (8192 x 1024) @ (1024 x 4096) + beta, with fused
    //    silu(u) tap into proj[:, 0:1024]
    gemm_tf32_kernel<<<dim3(N_UVQK / 128, Mrows / 128), 256>>>(
        normx, uvqk_w, uvqk, Mrows, N_UVQK, Esz, uvqk_beta, nullptr, proj);

    // 3) tensor-core attention -> attn
    attn_tc_kernel<<<dim3(Ssz / 64, Hsz, Bsz), 256, ATTN_SMEM_BYTES>>>(
        uvqk, num_targets, attn);

    // 4) LN(attn) + gate
    postattn_kernel<<<Mrows, 256>>>(attn, out_scale, out_bias, proj);

    // 5) output GEMM with fused residual
    gemm_tf32_kernel<<<dim3(Esz / 128, Mrows / 128), 256>>>(
        proj, out_w, out, Mrows, Esz, N_PROJ, nullptr, x, nullptr);
}

// round 5
// speedup vs baseline: 2.5693x; 1.2269x over previous
#include <cuda_runtime.h>
#include <math.h>
#include <stdint.h>

// ---------------- problem constants ----------------
#define Bsz   4
#define Ssz   2048
#define Esz   1024
#define Hsz   8
#define Mrows (Bsz * Ssz)          // 8192
#define N_UVQK 4096
#define N_PROJ 3072
#define ALPHA_SC 0.08838834764831845f   // 1/sqrt(128)
#define INV_S    (1.0f / 2048.0f)
#define LN_EPS   1e-6f

// ---------------- scratch (device globals; no allocation allowed) ----------------
__device__ float g_normx[(size_t)Mrows * Esz];    // 32 MB
__device__ float g_uvqk [(size_t)Mrows * N_UVQK]; // 128 MB
__device__ float g_attn [(size_t)Mrows * Esz];    // 32 MB
__device__ float g_proj [(size_t)Mrows * N_PROJ]; // 96 MB

// ---------------- helpers ----------------
__device__ __forceinline__ uint32_t f2tf32(float x) {
    uint32_t r;
    asm("cvt.rna.tf32.f32 %0, %1;" : "=r"(r) : "f"(x));
    return r;
}

__device__ __forceinline__ void mma_tf32(float* d,
    uint32_t a0, uint32_t a1, uint32_t a2, uint32_t a3,
    uint32_t b0, uint32_t b1)
{
    asm volatile(
        "mma.sync.aligned.m16n8k8.row.col.f32.tf32.tf32.f32 "
        "{%0,%1,%2,%3}, {%4,%5,%6,%7}, {%8,%9}, {%0,%1,%2,%3};\n"
        : "+f"(d[0]), "+f"(d[1]), "+f"(d[2]), "+f"(d[3])
        : "r"(a0), "r"(a1), "r"(a2), "r"(a3), "r"(b0), "r"(b1));
}

__device__ __forceinline__ float silu_f(float x) {
    return x / (1.0f + expf(-x));
}

__device__ __forceinline__ void blockReduce2(float& a, float& b) {
    #pragma unroll
    for (int off = 16; off > 0; off >>= 1) {
        a += __shfl_down_sync(0xffffffffu, a, off);
        b += __shfl_down_sync(0xffffffffu, b, off);
    }
    __shared__ float sa[8], sb[8];
    __shared__ float ra, rb;
    int w = threadIdx.x >> 5, l = threadIdx.x & 31;
    if (l == 0) { sa[w] = a; sb[w] = b; }
    __syncthreads();
    if (threadIdx.x == 0) {
        float ta = 0.f, tb = 0.f;
        #pragma unroll
        for (int i = 0; i < 8; i++) { ta += sa[i]; tb += sb[i]; }
        ra = ta; rb = tb;
    }
    __syncthreads();
    a = ra; b = rb;
}

// ---------------- LayerNorm on input x -> g_normx ----------------
__global__ __launch_bounds__(256) void ln_in_kernel(
    const float* __restrict__ x, const float* __restrict__ sc,
    const float* __restrict__ bi, float* __restrict__ out)
{
    int row = blockIdx.x;
    int c = threadIdx.x * 4;
    const float* xr = x + (size_t)row * Esz;
    float4 v = *(const float4*)&xr[c];
    float s  = v.x + v.y + v.z + v.w;
    float ss = v.x*v.x + v.y*v.y + v.z*v.z + v.w*v.w;
    blockReduce2(s, ss);
    float mu = s * (1.0f / Esz);
    float rs = rsqrtf(ss * (1.0f / Esz) - mu * mu + LN_EPS);
    float4 s4 = *(const float4*)&sc[c];
    float4 b4 = *(const float4*)&bi[c];
    float4 o;
    o.x = (v.x - mu) * rs * s4.x + b4.x;
    o.y = (v.y - mu) * rs * s4.y + b4.y;
    o.z = (v.z - mu) * rs * s4.z + b4.z;
    o.w = (v.w - mu) * rs * s4.w + b4.w;
    *(float4*)&out[(size_t)row * Esz + c] = o;
}

// ---------------- tf32 tensor-core GEMM, double-buffered smem ----------------
// A: MxK row-major fp32. B: KxN row-major fp32. Block tile 128x128, kTile 16.
// 8 warps in 2(M) x 4(N): warp tile 64x32 via m16n8k8. 2-stage smem pipeline.
// If silu_dst != null: for columns < 1024 also write silu(v) to
// silu_dst[row * N_PROJ + col]  (fuses the u -> silu(u) pass of GEMM1).
__global__ __launch_bounds__(256) void gemm_tf32_kernel(
    const float* __restrict__ A, const float* __restrict__ Bm,
    float* __restrict__ C, int M, int N, int K,
    const float* __restrict__ bias, const float* __restrict__ resid,
    float* __restrict__ silu_dst)
{
    __shared__ uint32_t As[2][16][132];   // [stage][k][m] (transposed)
    __shared__ uint32_t Bs[2][16][132];   // [stage][k][n]

    int tid = threadIdx.x;
    int wid = tid >> 5, lane = tid & 31;
    int gID = lane >> 2, tig = lane & 3;
    int warpM = wid & 1, warpN = wid >> 1;
    int bx = blockIdx.x, by = blockIdx.y;

    int arow = tid >> 1, acol = (tid & 1) * 8;
    int brow = tid >> 4, bcol = (tid & 15) * 8;
    const float* Aload = A + (size_t)(by * 128 + arow) * K + acol;
    const float* Bload = Bm + (size_t)brow * N + bx * 128 + bcol;

    float acc[4][4][4];
    #pragma unroll
    for (int i = 0; i < 4; i++)
        #pragma unroll
        for (int j = 0; j < 4; j++)
            #pragma unroll
            for (int q = 0; q < 4; q++) acc[i][j][q] = 0.f;

    float4 pa0, pa1, pb0, pb1;
    pa0 = *(const float4*)Aload;       pa1 = *(const float4*)(Aload + 4);
    pb0 = *(const float4*)Bload;       pb1 = *(const float4*)(Bload + 4);

    auto store_tiles = [&](int st) {
        As[st][acol + 0][arow] = f2tf32(pa0.x);
        As[st][acol + 1][arow] = f2tf32(pa0.y);
        As[st][acol + 2][arow] = f2tf32(pa0.z);
        As[st][acol + 3][arow] = f2tf32(pa0.w);
        As[st][acol + 4][arow] = f2tf32(pa1.x);
        As[st][acol + 5][arow] = f2tf32(pa1.y);
        As[st][acol + 6][arow] = f2tf32(pa1.z);
        As[st][acol + 7][arow] = f2tf32(pa1.w);
        Bs[st][brow][bcol + 0] = f2tf32(pb0.x);
        Bs[st][brow][bcol + 1] = f2tf32(pb0.y);
        Bs[st][brow][bcol + 2] = f2tf32(pb0.z);
        Bs[st][brow][bcol + 3] = f2tf32(pb0.w);
        Bs[st][brow][bcol + 4] = f2tf32(pb1.x);
        Bs[st][brow][bcol + 5] = f2tf32(pb1.y);
        Bs[st][brow][bcol + 6] = f2tf32(pb1.z);
        Bs[st][brow][bcol + 7] = f2tf32(pb1.w);
    };

    store_tiles(0);
    __syncthreads();

    int s = 0;
    for (int k0 = 0; k0 < K; k0 += 16) {
        bool more = (k0 + 16) < K;
        if (more) {
            Aload += 16;
            Bload += (size_t)16 * N;
            pa0 = *(const float4*)Aload;  pa1 = *(const float4*)(Aload + 4);
            pb0 = *(const float4*)Bload;  pb1 = *(const float4*)(Bload + 4);
        }
        #pragma unroll
        for (int ks = 0; ks < 2; ks++) {
            int kb = ks * 8;
            uint32_t af[4][4], bf[4][2];
            #pragma unroll
            for (int i = 0; i < 4; i++) {
                int m = warpM * 64 + i * 16 + gID;
                af[i][0] = As[s][kb + tig][m];
                af[i][1] = As[s][kb + tig][m + 8];
                af[i][2] = As[s][kb + tig + 4][m];
                af[i][3] = As[s][kb + tig + 4][m + 8];
            }
            #pragma unroll
            for (int j = 0; j < 4; j++) {
                int n = warpN * 32 + j * 8 + gID;
                bf[j][0] = Bs[s][kb + tig][n];
                bf[j][1] = Bs[s][kb + tig + 4][n];
            }
            #pragma unroll
            for (int i = 0; i < 4; i++)
                #pragma unroll
                for (int j = 0; j < 4; j++)
                    mma_tf32(acc[i][j], af[i][0], af[i][1], af[i][2], af[i][3],
                             bf[j][0], bf[j][1]);
        }
        if (more) {
            store_tiles(s ^ 1);
            __syncthreads();
            s ^= 1;
        }
    }

    // epilogue
    bool siluTile = (silu_dst != nullptr) && (bx * 128 < 1024);
    #pragma unroll
    for (int i = 0; i < 4; i++) {
        int r0 = by * 128 + warpM * 64 + i * 16 + gID;
        #pragma unroll
        for (int j = 0; j < 4; j++) {
            int cg = bx * 128 + warpN * 32 + j * 8 + tig * 2;
            float v0 = acc[i][j][0], v1 = acc[i][j][1];
            float v2 = acc[i][j][2], v3 = acc[i][j][3];
            if (bias) {
                float b0 = bias[cg], b1 = bias[cg + 1];
                v0 += b0; v1 += b1; v2 += b0; v3 += b1;
            }
            size_t o0 = (size_t)r0 * N + cg;
            size_t o1 = (size_t)(r0 + 8) * N + cg;
            if (resid) {
                v0 += resid[o0]; v1 += resid[o0 + 1];
                v2 += resid[o1]; v3 += resid[o1 + 1];
            }
            *(float2*)&C[o0] = make_float2(v0, v1);
            *(float2*)&C[o1] = make_float2(v2, v3);
            if (siluTile) {
                size_t p0 = (size_t)r0 * N_PROJ + cg;
                size_t p1 = (size_t)(r0 + 8) * N_PROJ + cg;
                *(float2*)&silu_dst[p0] = make_float2(silu_f(v0), silu_f(v1));
                *(float2*)&silu_dst[p1] = make_float2(silu_f(v2), silu_f(v3));
            }
        }
    }
}

// ---------------- tensor-core fused attention ----------------
// block = (b, h, 64 q rows). 256 threads / 8 warps. Two tf32 GEMMs per K-tile(64):
//   S = Q @ K^T  (64x64x128), then mask/silu -> Ws, then O += Ws @ V (64x128x64)
// Mask is lower-triangular (ids=min(i,maxid) is monotone), so K-tiles with
// k0 > q0 are identically zero and are skipped.
// Dynamic smem layout (uint32 words):
//   Qs [64][132] @ 0      Ks [64][132] @ 8448
//   Vs [64][132] @ 16896  Ws [64][68]  @ 25344     total 29696 words = 118784 B
#define QS(r,c) sm[(r) * 132 + (c)]
#define KS(r,c) sm[8448 + (r) * 132 + (c)]
#define VS(r,c) sm[16896 + (r) * 132 + (c)]
#define WS(r,c) sm[25344 + (r) * 68 + (c)]
#define ATTN_SMEM_BYTES (29696 * 4)

__global__ __launch_bounds__(256) void attn_tc_kernel(
    const float* __restrict__ uvqk, const int* __restrict__ num_targets,
    float* __restrict__ attn_out)
{
    extern __shared__ uint32_t sm[];
    int tid = threadIdx.x;
    int wid = tid >> 5, lane = tid & 31;
    int gID = lane >> 2, tig = lane & 3;
    int b = blockIdx.z, h = blockIdx.y;
    int q0 = blockIdx.x * 64;
    int maxid = Ssz - num_targets[b];

    const size_t rstride = N_UVQK;
    const float* qbase = uvqk + (size_t)(b * Ssz) * rstride + 2048 + h * 128;
    const float* kbase = uvqk + (size_t)(b * Ssz) * rstride + 3072 + h * 128;
    const float* vbase = uvqk + (size_t)(b * Ssz) * rstride + 1024 + h * 128;

    // load Q tile (64 x 128)
    {
        int r = tid >> 2, cb = (tid & 3) * 32;
        const float* src = qbase + (size_t)(q0 + r) * rstride + cb;
        #pragma unroll
        for (int x = 0; x < 8; x++) {
            float4 v = *(const float4*)(src + x * 4);
            QS(r, cb + x * 4 + 0) = f2tf32(v.x);
            QS(r, cb + x * 4 + 1) = f2tf32(v.y);
            QS(r, cb + x * 4 + 2) = f2tf32(v.z);
            QS(r, cb + x * 4 + 3) = f2tf32(v.w);
        }
    }

    // score warps: 4(M) x 2(N); output warps: 2(M) x 4(N)
    int sWM = wid & 3, sWN = wid >> 2;
    int oWM = wid & 1, oWN = wid >> 1;

    float acc_o[2][4][4];
    #pragma unroll
    for (int i = 0; i < 2; i++)
        #pragma unroll
        for (int j = 0; j < 4; j++)
            #pragma unroll
            for (int q = 0; q < 4; q++) acc_o[i][j][q] = 0.f;

    int ldr = tid >> 2, ldc = (tid & 3) * 32;

    // mask is zero for all k > q: only k0 <= q0 tiles contribute
    for (int k0 = 0; k0 <= q0; k0 += 64) {
        __syncthreads();   // previous iteration's reads of Ks/Vs/Ws complete
        // load K and V tiles (64 x 128 each)
        {
            const float* ksrc = kbase + (size_t)(k0 + ldr) * rstride + ldc;
            const float* vsrc = vbase + (size_t)(k0 + ldr) * rstride + ldc;
            #pragma unroll
            for (int x = 0; x < 8; x++) {
                float4 kv = *(const float4*)(ksrc + x * 4);
                KS(ldr, ldc + x * 4 + 0) = f2tf32(kv.x);
                KS(ldr, ldc + x * 4 + 1) = f2tf32(kv.y);
                KS(ldr, ldc + x * 4 + 2) = f2tf32(kv.z);
                KS(ldr, ldc + x * 4 + 3) = f2tf32(kv.w);
            }
            #pragma unroll
            for (int x = 0; x < 8; x++) {
                float4 vv = *(const float4*)(vsrc + x * 4);
                VS(ldr, ldc + x * 4 + 0) = f2tf32(vv.x);
                VS(ldr, ldc + x * 4 + 1) = f2tf32(vv.y);
                VS(ldr, ldc + x * 4 + 2) = f2tf32(vv.z);
                VS(ldr, ldc + x * 4 + 3) = f2tf32(vv.w);
            }
        }
        __syncthreads();

        // scores: S(64x64) = Q(64x128) @ K^T
        float acc_s[4][4];
        #pragma unroll
        for (int j = 0; j < 4; j++)
            #pragma unroll
            for (int q = 0; q < 4; q++) acc_s[j][q] = 0.f;

        #pragma unroll
        for (int ks = 0; ks < 16; ks++) {
            int kb = ks * 8;
            int m = sWM * 16 + gID;
            uint32_t a0 = QS(m, kb + tig);
            uint32_t a1 = QS(m + 8, kb + tig);
            uint32_t a2 = QS(m, kb + tig + 4);
            uint32_t a3 = QS(m + 8, kb + tig + 4);
            #pragma unroll
            for (int j = 0; j < 4; j++) {
                int n = sWN * 32 + j * 8 + gID;
                uint32_t b0 = KS(n, kb + tig);
                uint32_t b1 = KS(n, kb + tig + 4);
                mma_tf32(acc_s[j], a0, a1, a2, a3, b0, b1);
            }
        }

        // mask + silu -> Ws
        {
            int rowL = sWM * 16 + gID;
            int qg0 = q0 + rowL;
            int qg1 = qg0 + 8;
            int idq0 = min(qg0, maxid);
            int idq1 = min(qg1, maxid);
            #pragma unroll
            for (int j = 0; j < 4; j++) {
                int colL = sWN * 32 + j * 8 + tig * 2;
                #pragma unroll
                for (int cc = 0; cc < 2; cc++) {
                    int kg = k0 + colL + cc;
                    int idk = min(kg, maxid);
                    float s0 = acc_s[j][cc] * ALPHA_SC;
                    float s1 = acc_s[j][cc + 2] * ALPHA_SC;
                    bool v0 = (qg0 == kg) || (idq0 > idk);
                    bool v1 = (qg1 == kg) || (idq1 > idk);
                    float w0 = v0 ? silu_f(s0) * INV_S : 0.f;
                    float w1 = v1 ? silu_f(s1) * INV_S : 0.f;
                    WS(rowL, colL + cc)     = f2tf32(w0);
                    WS(rowL + 8, colL + cc) = f2tf32(w1);
                }
            }
        }
        __syncthreads();

        // O += Ws(64x64) @ V(64x128)
        #pragma unroll
        for (int ks = 0; ks < 8; ks++) {
            int kb = ks * 8;
            uint32_t af[2][4];
            #pragma unroll
            for (int i = 0; i < 2; i++) {
                int m = oWM * 32 + i * 16 + gID;
                af[i][0] = WS(m, kb + tig);
                af[i][1] = WS(m + 8, kb + tig);
                af[i][2] = WS(m, kb + tig + 4);
                af[i][3] = WS(m + 8, kb + tig + 4);
            }
            #pragma unroll
            for (int j = 0; j < 4; j++) {
                int n = oWN * 32 + j * 8 + gID;
                uint32_t b0 = VS(kb + tig, n);
                uint32_t b1 = VS(kb + tig + 4, n);
                #pragma unroll
                for (int i = 0; i < 2; i++)
                    mma_tf32(acc_o[i][j], af[i][0], af[i][1], af[i][2], af[i][3],
                             b0, b1);
            }
        }
    }

    // epilogue
    #pragma unroll
    for (int i = 0; i < 2; i++) {
        int rowL = oWM * 32 + i * 16 + gID;
        size_t grow0 = (size_t)(b * Ssz + q0 + rowL) * Esz;
        size_t grow1 = (size_t)(b * Ssz + q0 + rowL + 8) * Esz;
        #pragma unroll
        for (int j = 0; j < 4; j++) {
            int col = h * 128 + oWN * 32 + j * 8 + tig * 2;
            *(float2*)&attn_out[grow0 + col] = make_float2(acc_o[i][j][0], acc_o[i][j][1]);
            *(float2*)&attn_out[grow1 + col] = make_float2(acc_o[i][j][2], acc_o[i][j][3]);
        }
    }
}

// ---------------- post-attention: LN(attn), gate, fill proj ----------------
__global__ __launch_bounds__(256) void postattn_kernel(
    const float* __restrict__ attn, const float* __restrict__ sc,
    const float* __restrict__ bi, float* __restrict__ proj)
{
    int row = blockIdx.x;
    int c = threadIdx.x * 4;
    const float* ar = attn + (size_t)row * Esz;
    float4 a = *(const float4*)&ar[c];
    float s  = a.x + a.y + a.z + a.w;
    float ss = a.x*a.x + a.y*a.y + a.z*a.z + a.w*a.w;
    blockReduce2(s, ss);
    float mu = s * (1.0f / Esz);
    float rs = rsqrtf(ss * (1.0f / Esz) - mu * mu + LN_EPS);
    float4 s4 = *(const float4*)&sc[c];
    float4 b4 = *(const float4*)&bi[c];
    float4 n;
    n.x = (a.x - mu) * rs * s4.x + b4.x;
    n.y = (a.y - mu) * rs * s4.y + b4.y;
    n.z = (a.z - mu) * rs * s4.z + b4.z;
    n.w = (a.w - mu) * rs * s4.w + b4.w;
    float* pr = proj + (size_t)row * N_PROJ;
    float4 u = *(const float4*)&pr[c];
    *(float4*)&pr[1024 + c] = a;
    float4 g;
    g.x = u.x * n.x; g.y = u.y * n.y; g.z = u.z * n.z; g.w = u.w * n.w;
    *(float4*)&pr[2048 + c] = g;
}

// ---------------- launch ----------------
extern "C" void kernel_launch(void* const* d_in, const int* in_sizes, int n_in,
                              void* d_out, int out_size)
{
    const float* x           = (const float*)d_in[0];
    const int*   num_targets = (const int*)  d_in[1];
    const float* uvqk_w      = (const float*)d_in[2];
    const float* uvqk_beta   = (const float*)d_in[3];
    const float* out_w       = (const float*)d_in[4];
    const float* in_scale    = (const float*)d_in[5];
    const float* in_bias     = (const float*)d_in[6];
    const float* out_scale   = (const float*)d_in[7];
    const float* out_bias    = (const float*)d_in[8];
    float* out = (float*)d_out;

    float *normx, *uvqk, *attn, *proj;
    cudaGetSymbolAddress((void**)&normx, g_normx);
    cudaGetSymbolAddress((void**)&uvqk,  g_uvqk);
    cudaGetSymbolAddress((void**)&attn,  g_attn);
    cudaGetSymbolAddress((void**)&proj,  g_proj);

    // idempotent, capture-safe (not a stream operation); no static state
    cudaFuncSetAttribute(attn_tc_kernel,
                         cudaFuncAttributeMaxDynamicSharedMemorySize,
                         ATTN_SMEM_BYTES);

    // 1) LayerNorm input
    ln_in_kernel<<<Mrows, 256>>>(x, in_scale, in_bias, normx);

    // 2) UVQK GEMM: (8192 x 1024) @ (1024 x 4096) + beta, with fused
    //    silu(u) tap into proj[:, 0:1024]
    gemm_tf32_kernel<<<dim3(N_UVQK / 128, Mrows / 128), 256>>>(
        normx, uvqk_w, uvqk, Mrows, N_UVQK, Esz, uvqk_beta, nullptr, proj);

    // 3) tensor-core attention (causal-skip) -> attn
    attn_tc_kernel<<<dim3(Ssz / 64, Hsz, Bsz), 256, ATTN_SMEM_BYTES>>>(
        uvqk, num_targets, attn);

    // 4) LN(attn) + gate
    postattn_kernel<<<Mrows, 256>>>(attn, out_scale, out_bias, proj);

    // 5) output GEMM with fused residual
    gemm_tf32_kernel<<<dim3(Esz / 128, Mrows / 128), 256>>>(
        proj, out_w, out, Mrows, Esz, N_PROJ, nullptr, x, nullptr);
}